// round 9
// baseline (speedup 1.0000x reference)
#include <cuda_runtime.h>
#include <cstdint>
#include <math.h>

#define CS     8      // CTAs per batch (row slabs)
#define ROWS   24     // rows per CTA
#define PITCH  196    // 2 guard cols + 192 data + 2 guard cols
#define LROWS  26     // ROWS + 2 halo rows
#define NG     192
#define TSTEPS 256
#define NTHR   768
#define KPT    6      // rows per thread (4 row-groups of 192 threads)

__device__ __forceinline__ uint32_t s2u(const void* p) {
    return (uint32_t)__cvta_generic_to_shared((void*)p);
}
__device__ __forceinline__ uint32_t mapa_u32(uint32_t a, uint32_t r) {
    uint32_t d;
    asm("mapa.shared::cluster.u32 %0, %1, %2;" : "=r"(d) : "r"(a), "r"(r));
    return d;
}
__device__ __forceinline__ void st_cluster_f32(uint32_t a, float v) {
    asm volatile("st.shared::cluster.f32 [%0], %1;" :: "r"(a), "f"(v) : "memory");
}
__device__ __forceinline__ void cl_arrive() {
    asm volatile("barrier.cluster.arrive.aligned;" ::: "memory");
}
__device__ __forceinline__ void cl_wait() {
    asm volatile("barrier.cluster.wait.aligned;" ::: "memory");
}
__device__ __forceinline__ void mbar_init(uint32_t a, uint32_t cnt) {
    asm volatile("mbarrier.init.shared.b64 [%0], %1;" :: "r"(a), "r"(cnt) : "memory");
}
__device__ __forceinline__ void mbar_arrive_remote(uint32_t remAddr) {
    asm volatile("mbarrier.arrive.release.cluster.shared::cluster.b64 _, [%0];"
                 :: "r"(remAddr) : "memory");
}
__device__ __forceinline__ void mbar_wait(uint32_t addr, uint32_t parity) {
    asm volatile(
        "{\n\t"
        ".reg .pred P;\n\t"
        "WL_%=:\n\t"
        "mbarrier.try_wait.parity.acquire.cluster.shared::cta.b64 P, [%0], %1, 0x989680;\n\t"
        "@P bra.uni WD_%=;\n\t"
        "bra.uni WL_%=;\n\t"
        "WD_%=:\n\t"
        "}"
        :: "r"(addr), "r"(parity) : "memory");
}

// PML 1D profile: v[k] = 3*(k/20)^4
__device__ __forceinline__ float pml1(int i) {
    int d;
    if (i <= 20)           d = 20 - i;
    else if (i >= NG - 21) d = i - (NG - 21);
    else return 0.0f;
    double t = (double)d * 0.05;
    double t2 = t * t;
    return (float)(3.0 * t2 * t2);
}

__global__ void __cluster_dims__(CS, 1, 1) __launch_bounds__(NTHR, 1)
wave_kernel(const float* __restrict__ x, const float* __restrict__ rho,
            float* __restrict__ out)
{
    __shared__ float bufs[2][LROWS * PITCH];  // double-buffered field, rows -1..24
    __shared__ float xs[TSTEPS];
    __shared__ float pbuf[3];
    // two barriers per side, ping-pong by step parity (alias-proof)
    __shared__ alignas(8) unsigned long long mbTopA[2], mbBotA[2];

    const int tid   = threadIdx.x;
    const int col   = tid % NG;       // 0..191
    const int rgrp  = tid / NG;       // 0..3 (rows 6*rgrp .. 6*rgrp+5)
    const int rank  = blockIdx.x % CS;
    const int batch = blockIdx.x / CS;

    for (int i = tid; i < 2 * LROWS * PITCH; i += NTHR) (&bufs[0][0])[i] = 0.f;
    for (int i = tid; i < TSTEPS; i += NTHR) xs[i] = x[batch * TSTEPS + i];
    if (tid == 0) {
        mbar_init(s2u(&mbTopA[0]), NG); mbar_init(s2u(&mbTopA[1]), NG);
        mbar_init(s2u(&mbBotA[0]), NG); mbar_init(s2u(&mbBotA[1]), NG);
    }

    // ---- per-cell coefficients: yn = Qp*c - Qm*y2 + Rc*(n+s+w+e) ----
    const float HM2 = (float)(1.0 / (2.01 * 2.01));
    float Qp[KPT], Qm[KPT], Rc[KPT], y2[KPT];
#pragma unroll
    for (int k = 0; k < KPT; ++k) {
        const int g = rank * ROWS + rgrp * KPT + k;
        float cc = rho[g * NG + col];
        float nn = (g > 0)      ? rho[(g - 1) * NG + col] : 0.f;
        float ss = (g < NG - 1) ? rho[(g + 1) * NG + col] : 0.f;
        float ww = (col > 0)    ? rho[g * NG + col - 1]   : 0.f;
        float ee = (col < NG-1) ? rho[g * NG + col + 1]   : 0.f;
        float lpf = 0.5f * cc + 0.125f * (nn + ss + ww + ee);
        float pr  = (1.0f + tanhf(100.0f * (lpf - 0.5f))) * 0.5f;
        float c   = 1.0f - 0.1f * pr;
        float bx = pml1(g), by = pml1(col);
        float bb = sqrtf(bx * bx + by * by);
        float A1 = 1.0f / (1.0f + 0.5f * bb);
        float Q  = A1 * (1.0f - 0.5f * bb);
        float R  = A1 * (c * c) * HM2;
        Qp[k] = 1.0f + Q - 4.0f * R;
        Qm[k] = Q;
        Rc[k] = R;
        y2[k] = 0.f;
    }

    const int base = rgrp * KPT + 1;
    const float* p0 = &bufs[0][base * PITCH + col + 2];
    const float* p1 = &bufs[1][base * PITCH + col + 2];

    const bool gTop = (rgrp == 0), gBot = (rgrp == 3);
    const bool doUp = gTop && (rank > 0);
    const bool doDn = gBot && (rank < CS - 1);
    uint32_t upA[2] = {0,0}, dnA[2] = {0,0}, mbRem[2] = {0,0}, mbOwn[2] = {0,0};
    if (doUp) {
        upA[0] = mapa_u32(s2u(&bufs[0][(ROWS + 1) * PITCH + col + 2]), (uint32_t)(rank - 1));
        upA[1] = mapa_u32(s2u(&bufs[1][(ROWS + 1) * PITCH + col + 2]), (uint32_t)(rank - 1));
        mbRem[0] = mapa_u32(s2u(&mbBotA[0]), (uint32_t)(rank - 1));
        mbRem[1] = mapa_u32(s2u(&mbBotA[1]), (uint32_t)(rank - 1));
        mbOwn[0] = s2u(&mbTopA[0]); mbOwn[1] = s2u(&mbTopA[1]);
    }
    if (doDn) {
        dnA[0] = mapa_u32(s2u(&bufs[0][col + 2]), (uint32_t)(rank + 1));
        dnA[1] = mapa_u32(s2u(&bufs[1][col + 2]), (uint32_t)(rank + 1));
        mbRem[0] = mapa_u32(s2u(&mbTopA[0]), (uint32_t)(rank + 1));
        mbRem[1] = mapa_u32(s2u(&mbTopA[1]), (uint32_t)(rank + 1));
        mbOwn[0] = s2u(&mbBotA[0]); mbOwn[1] = s2u(&mbBotA[1]);
    }

    // Source (40,96): rank1, rgrp2, k=4. Probes (160,{48,96,144}): rank6, rgrp2, k=4.
    const bool isSrc = (rank == 1) && (rgrp == 2) && (col == 96);
    const bool isPrb = (rank == 6) && (rgrp == 2) &&
                       ((col == 48) | (col == 96) | (col == 144));
    float pacc = 0.f;

    cl_arrive(); cl_wait();   // zeros + mbarrier init visible cluster-wide

    for (int t = 0; t < TSTEPS; ++t) {
        const int wb = (t & 1) ^ 1;
        const float* rp = (t & 1) ? p1 : p0;
        float* wp = const_cast<float*>((t & 1) ? p0 : p1);
        // wait schedule: barrier (t-1)&1, parity ((t-1)>>1)&1 (only for t>0)
        const uint32_t wBi  = (uint32_t)((t - 1) & 1);
        const uint32_t wPar = (uint32_t)(((t - 1) >> 1) & 1);
        const uint32_t aBi  = (uint32_t)(t & 1);

        if (gTop) {
            // rows 1..5 first (no halo dependency)
            float r0old = rp[0];
            float n = r0old;
            float c = rp[PITCH];
#pragma unroll
            for (int k = 1; k < KPT; ++k) {
                float s  = rp[(k + 1) * PITCH];
                float wv = rp[k * PITCH - 1];
                float ev = rp[k * PITCH + 1];
                float yn = fmaf(Qp[k], c, fmaf(-Qm[k], y2[k], Rc[k] * ((n + s) + (wv + ev))));
                wp[k * PITCH] = yn;
                y2[k] = c; n = c; c = s;
            }
            if (doUp) {
                if (t > 0) mbar_wait(mbOwn[wBi], wPar);
                float hn = rp[-PITCH];
                float wv = rp[-1], ev = rp[1];
                float yn = fmaf(Qp[0], r0old,
                           fmaf(-Qm[0], y2[0], Rc[0] * ((hn + y2[1]) + (wv + ev))));
                y2[0] = r0old;
                wp[0] = yn;
                st_cluster_f32(upA[wb], yn);       // y(t+1) row 0 -> nbr halo row 24
                mbar_arrive_remote(mbRem[aBi]);    // all 192 threads arrive
            } else {
                float hn = rp[-PITCH];             // stays zero at rank 0
                float wv = rp[-1], ev = rp[1];
                float yn = fmaf(Qp[0], r0old,
                           fmaf(-Qm[0], y2[0], Rc[0] * ((hn + y2[1]) + (wv + ev))));
                y2[0] = r0old;
                wp[0] = yn;
            }
        } else if (gBot) {
            // rows 18..22 (k=0..4) first
            float n = rp[-PITCH];
            float c = rp[0];
#pragma unroll
            for (int k = 0; k < KPT - 1; ++k) {
                float s  = rp[(k + 1) * PITCH];
                float wv = rp[k * PITCH - 1];
                float ev = rp[k * PITCH + 1];
                float yn = fmaf(Qp[k], c, fmaf(-Qm[k], y2[k], Rc[k] * ((n + s) + (wv + ev))));
                wp[k * PITCH] = yn;
                y2[k] = c; n = c; c = s;
            }
            const int k = KPT - 1;
            if (doDn) {
                if (t > 0) mbar_wait(mbOwn[wBi], wPar);
                float hs = rp[(k + 1) * PITCH];
                float wv = rp[k * PITCH - 1], ev = rp[k * PITCH + 1];
                float yn = fmaf(Qp[k], c, fmaf(-Qm[k], y2[k], Rc[k] * ((n + hs) + (wv + ev))));
                y2[k] = c;
                wp[k * PITCH] = yn;
                st_cluster_f32(dnA[wb], yn);       // y(t+1) row 23 -> nbr halo row -1
                mbar_arrive_remote(mbRem[aBi]);
            } else {
                float hs = rp[(k + 1) * PITCH];    // stays zero at rank CS-1
                float wv = rp[k * PITCH - 1], ev = rp[k * PITCH + 1];
                float yn = fmaf(Qp[k], c, fmaf(-Qm[k], y2[k], Rc[k] * ((n + hs) + (wv + ev))));
                y2[k] = c;
                wp[k * PITCH] = yn;
            }
        } else {
            // interior row-groups: no cluster interaction
            float n = rp[-PITCH];
            float c = rp[0];
#pragma unroll
            for (int k = 0; k < KPT; ++k) {
                float s  = rp[(k + 1) * PITCH];
                float wv = rp[k * PITCH - 1];
                float ev = rp[k * PITCH + 1];
                float yn = fmaf(Qp[k], c, fmaf(-Qm[k], y2[k], Rc[k] * ((n + s) + (wv + ev))));
                if (k == 4) {
                    if (isSrc) yn += xs[t];
                    if (isPrb) pacc = fmaf(yn, yn, pacc);
                }
                wp[k * PITCH] = yn;
                y2[k] = c; n = c; c = s;
            }
        }
        __syncthreads();   // one CTA-wide join per step
    }

    cl_arrive(); cl_wait();   // quiesce in-flight DSMEM before any CTA exits

    if (isPrb) pbuf[(col - 48) / 48] = pacc;
    __syncthreads();
    if (rank == 6 && tid == 0) {
        float a = pbuf[0], b = pbuf[1], cc = pbuf[2];
        float sum = a + b + cc;
        out[batch * 3 + 0] = a / sum;
        out[batch * 3 + 1] = b / sum;
        out[batch * 3 + 2] = cc / sum;
    }
}

extern "C" void kernel_launch(void* const* d_in, const int* in_sizes, int n_in,
                              void* d_out, int out_size)
{
    (void)in_sizes; (void)n_in; (void)out_size;
    const float* x   = (const float*)d_in[0];   // (4,256) f32
    const float* rho = (const float*)d_in[1];   // (192,192) f32
    float* out = (float*)d_out;                 // (4,3) f32
    wave_kernel<<<dim3(CS * 4), dim3(NTHR)>>>(x, rho, out);
}

// round 10
// speedup vs baseline: 1.4604x; 1.4604x over previous
#include <cuda_runtime.h>
#include <cstdint>
#include <math.h>

#define CS     8
#define NG     192
#define P      196               // row pitch in floats (2 guard + 192 + 2 guard)
#define FROWS  24
#define NTHR   768
#define TSTEPS 256
#define NBLK   (TSTEPS / 2)
#define BUFSZ  (FROWS * P)
#define HALOSZ (2 * 2 * 2 * P)   // [parity][side][idx: 0=row∓1,1=row∓2][P]
#define SMEMFLOATS (3 * BUFSZ + HALOSZ + TSTEPS + 8)

__device__ __forceinline__ uint32_t s2u(const void* p) {
    return (uint32_t)__cvta_generic_to_shared((void*)p);
}
__device__ __forceinline__ uint32_t mapa_u32(uint32_t a, uint32_t r) {
    uint32_t d;
    asm("mapa.shared::cluster.u32 %0, %1, %2;" : "=r"(d) : "r"(a), "r"(r));
    return d;
}
__device__ __forceinline__ void st_cluster_f32(uint32_t a, float v) {
    asm volatile("st.shared::cluster.f32 [%0], %1;" :: "r"(a), "f"(v) : "memory");
}
__device__ __forceinline__ void cl_arrive() {
    asm volatile("barrier.cluster.arrive.aligned;" ::: "memory");
}
__device__ __forceinline__ void cl_wait() {
    asm volatile("barrier.cluster.wait.aligned;" ::: "memory");
}
__device__ __forceinline__ void rgrp_bar(int id) {
    asm volatile("bar.sync %0, %1;" :: "r"(id), "r"(192) : "memory");
}

__device__ __forceinline__ float pml1(int i) {
    int d;
    if (i <= 20)           d = 20 - i;
    else if (i >= NG - 21) d = i - (NG - 21);
    else return 0.0f;
    double t = (double)d * 0.05;
    double t2 = t * t;
    return (float)(3.0 * t2 * t2);
}

__global__ void __cluster_dims__(CS, 1, 1) __launch_bounds__(NTHR, 1)
wave_kernel(const float* __restrict__ x, const float* __restrict__ rho,
            float* __restrict__ out)
{
    extern __shared__ float dsm[];
    float* bufA = dsm;
    float* bufB = dsm + BUFSZ;
    float* bufC = dsm + 2 * BUFSZ;
    float* halo = dsm + 3 * BUFSZ;
    float* xs   = halo + HALOSZ;
    float* pbuf = xs + TSTEPS;

    const int tid   = threadIdx.x;
    const int col   = tid % NG;
    const int rgrp  = tid / NG;            // 0..3, owns rows 6*rgrp..6*rgrp+5
    const int rank  = blockIdx.x % CS;
    const int batch = blockIdx.x / CS;

    for (int i = tid; i < 3 * BUFSZ + HALOSZ; i += NTHR) dsm[i] = 0.f;
    for (int i = tid; i < TSTEPS; i += NTHR) xs[i] = x[batch * TSTEPS + i];

    // ---- coefficients for 8 rows: j=0..7 <-> local row 6*rgrp + j - 1 ----
    const float HM2 = (float)(1.0 / (2.01 * 2.01));
    float Qp[8], Qm[8], Rc[8], y2[8], v[8];
#pragma unroll
    for (int j = 0; j < 8; ++j) {
        int g = rank * FROWS + rgrp * 6 + j - 1;
        int gc = min(max(g, 0), NG - 1);
        float cc = rho[gc * NG + col];
        float nn = (gc > 0)      ? rho[(gc - 1) * NG + col] : 0.f;
        float ss = (gc < NG - 1) ? rho[(gc + 1) * NG + col] : 0.f;
        float ww = (col > 0)     ? rho[gc * NG + col - 1]   : 0.f;
        float ee = (col < NG-1)  ? rho[gc * NG + col + 1]   : 0.f;
        float lpf = 0.5f * cc + 0.125f * (nn + ss + ww + ee);
        float pr  = (1.0f + tanhf(100.0f * (lpf - 0.5f))) * 0.5f;
        float c   = 1.0f - 0.1f * pr;
        float bx = pml1(gc), by = pml1(col);
        float bb = sqrtf(bx * bx + by * by);
        float A1 = 1.0f / (1.0f + 0.5f * bb);
        float Q  = A1 * (1.0f - 0.5f * bb);
        float R  = A1 * (c * c) * HM2;
        Qp[j] = 1.0f + Q - 4.0f * R;
        Qm[j] = Q;
        Rc[j] = R;
        y2[j] = 0.f; v[j] = 0.f;
    }

    const bool topR = (rgrp == 0), botR = (rgrp == 3);
    const bool doUp = topR && (rank > 0);
    const bool doDn = botR && (rank < CS - 1);

    // halo read pointers (valid for topR/botR)
    const int side = botR ? 1 : 0;
    const float* ph1[2]; const float* ph0[2];
#pragma unroll
    for (int p = 0; p < 2; ++p) {
        ph1[p] = halo + ((p * 2 + side) * 2 + 0) * P + col + 2;  // y(t) row ∓1
        ph0[p] = halo + ((p * 2 + side) * 2 + 1) * P + col + 2;  // y(t) row ∓2
    }
    uint32_t pa1[2] = {0,0}, pa0[2] = {0,0};
    if (doUp | doDn) {
        int nr = doUp ? rank - 1 : rank + 1;
        int ts = doUp ? 1 : 0;     // target side in neighbor
#pragma unroll
        for (int p = 0; p < 2; ++p) {
            pa1[p] = mapa_u32(s2u(halo + ((p * 2 + ts) * 2 + 0) * P + col + 2), (uint32_t)nr);
            pa0[p] = mapa_u32(s2u(halo + ((p * 2 + ts) * 2 + 1) * P + col + 2), (uint32_t)nr);
        }
    }

    const int ofs = rgrp * 6 * P + col + 2;   // buffer offset of own row 0
    float* pr_ = bufA + ofs;    // y(t)
    float* pm_ = bufB + ofs;    // y(t+1)
    float* po_ = bufC + ofs;    // y(t+2)

    // Source (40,96): rank1 rgrp2 j=5. Probes (160,{48,96,144}): rank6 rgrp2 j=5.
    const bool isSrc = (rank == 1) && (rgrp == 2) && (col == 96);
    const bool isPrb = (rank == 6) && (rgrp == 2) &&
                       ((col == 48) | (col == 96) | (col == 144));
    float pacc = 0.f;

    cl_arrive(); cl_wait();   // zeros + setup visible cluster-wide

    for (int b = 0; b < NBLK; ++b) {
        const int hp = b & 1, hq = hp ^ 1;
        const float xs1 = xs[2 * b];
        const float xs2 = xs[2 * b + 1];

        // ================= step 1: t -> t+1, rows j=0..7 (6 own + 2 ext) ====
        if (topR) {
            const float* h1c = ph1[hp];
            float hc = h1c[0];                 // y(t) row -1
            float hn = ph0[hp][0];             // y(t) row -2
            float hw = h1c[-1], he = h1c[1];
            float c  = pr_[0];                 // y(t) row 0
            {   // j=0: CTA-ext row -1
                float yn = fmaf(Qp[0], hc, fmaf(-Qm[0], y2[0], Rc[0] * ((hn + c) + (hw + he))));
                if (!doUp) yn = 0.f;
                v[0] = yn; y2[0] = hc;
            }
            float n = hc;
#pragma unroll
            for (int j = 1; j < 8; ++j) {
                float s = pr_[j * P];
                float w = pr_[(j - 1) * P - 1], e = pr_[(j - 1) * P + 1];
                float yn = fmaf(Qp[j], c, fmaf(-Qm[j], y2[j], Rc[j] * ((n + s) + (w + e))));
                if (j < 7) pm_[(j - 1) * P] = yn;
                v[j] = yn; y2[j] = c; n = c; c = s;
            }
        } else if (botR) {
            const float* h1c = ph1[hp];
            float hc = h1c[0];                 // y(t) row 24
            float n = pr_[-2 * P];             // row 16
            float c = pr_[-P];                 // row 17
#pragma unroll
            for (int j = 0; j < 7; ++j) {
                float s = (j == 6) ? hc : pr_[j * P];
                float w = pr_[(j - 1) * P - 1], e = pr_[(j - 1) * P + 1];
                float yn = fmaf(Qp[j], c, fmaf(-Qm[j], y2[j], Rc[j] * ((n + s) + (w + e))));
                if (j >= 1) pm_[(j - 1) * P] = yn;
                v[j] = yn; y2[j] = c; n = c; c = s;
            }
            {   // j=7: CTA-ext row 24 (n = row 23 value, rolled into n; c = hc)
                float hs = ph0[hp][0];         // y(t) row 25
                float hw = h1c[-1], he = h1c[1];
                float yn = fmaf(Qp[7], c, fmaf(-Qm[7], y2[7], Rc[7] * ((n + hs) + (hw + he))));
                if (!doDn) yn = 0.f;
                v[7] = yn; y2[7] = c;
            }
        } else {
            float n = pr_[-2 * P];
            float c = pr_[-P];
#pragma unroll
            for (int j = 0; j < 8; ++j) {
                float s = pr_[j * P];
                float w = pr_[(j - 1) * P - 1], e = pr_[(j - 1) * P + 1];
                float yn = fmaf(Qp[j], c, fmaf(-Qm[j], y2[j], Rc[j] * ((n + s) + (w + e))));
                if (j == 5) {
                    if (isSrc) yn += xs1;
                    if (isPrb) pacc = fmaf(yn, yn, pacc);
                }
                if (j >= 1 && j < 7) pm_[(j - 1) * P] = yn;
                v[j] = yn; y2[j] = c; n = c; c = s;
            }
        }
        rgrp_bar(rgrp + 1);   // orders step-1 pm writes within this rgrp only

        // ================= step 2: t+1 -> t+2, own rows j=1..6 ==============
        // N/S from v[] regs; W/E from pm (own-rgrp rows only); y2 = y(t) regs.
        auto s2 = [&](int j) -> float {
            float c = v[j];
            float w = pm_[(j - 1) * P - 1], e = pm_[(j - 1) * P + 1];
            float yn = fmaf(Qp[j], c, fmaf(-Qm[j], y2[j],
                        Rc[j] * ((v[j - 1] + v[j + 1]) + (w + e))));
            if (j == 5) {
                if (isSrc) yn += xs2;
                if (isPrb) pacc = fmaf(yn, yn, pacc);
            }
            po_[(j - 1) * P] = yn;
            y2[j] = c;
            return yn;
        };

        if (botR) {
            float a0 = s2(6), a1 = s2(5);      // rows 23, 22
            if (doDn) {
                st_cluster_f32(pa1[hq], a0);   // y(t+2) row 23 -> nbr row -1 slot
                st_cluster_f32(pa0[hq], a1);   // y(t+2) row 22 -> nbr row -2 slot
            }
        } else {
            float a0 = s2(1), a1 = s2(2);      // rows 0, 1
            if (doUp) {
                st_cluster_f32(pa1[hq], a0);   // y(t+2) row 0 -> nbr row 24 slot
                st_cluster_f32(pa0[hq], a1);   // y(t+2) row 1 -> nbr row 25 slot
            }
        }
        cl_arrive();   // release pushes; remaining rows overlap barrier

        if (botR) { s2(4); s2(3); s2(2); s2(1); }
        else      { s2(3); s2(4); s2(5); s2(6); }
        y2[0] = v[0]; y2[7] = v[7];   // ext y2 for next block = y(t+1) ext rows

        __syncthreads();   // y(t+2) (po) visible CTA-wide for next block's step 1
        cl_wait();         // neighbors' halo pushes visible

        // rotate buffers: new (read, mid, out) = (out, read, mid)
        float* t0 = pr_; pr_ = po_; po_ = pm_; pm_ = t0;
    }

    if (isPrb) pbuf[(col - 48) / 48] = pacc;
    __syncthreads();
    if (rank == 6 && tid == 0) {
        float a = pbuf[0], b = pbuf[1], c = pbuf[2];
        float s = a + b + c;
        out[batch * 3 + 0] = a / s;
        out[batch * 3 + 1] = b / s;
        out[batch * 3 + 2] = c / s;
    }
}

extern "C" void kernel_launch(void* const* d_in, const int* in_sizes, int n_in,
                              void* d_out, int out_size)
{
    (void)in_sizes; (void)n_in; (void)out_size;
    const float* x   = (const float*)d_in[0];   // (4,256) f32
    const float* rho = (const float*)d_in[1];   // (192,192) f32
    float* out = (float*)d_out;                 // (4,3) f32
    cudaFuncSetAttribute(wave_kernel,
                         cudaFuncAttributeMaxDynamicSharedMemorySize,
                         SMEMFLOATS * (int)sizeof(float));
    wave_kernel<<<dim3(CS * 4), dim3(NTHR), SMEMFLOATS * sizeof(float)>>>(x, rho, out);
}

// round 11
// speedup vs baseline: 1.8696x; 1.2802x over previous
#include <cuda_runtime.h>
#include <cstdint>
#include <math.h>

#define CS     16
#define NG     192
#define P      196               // row pitch (2 guard + 192 + 2 guard)
#define FROWS  12                // rows per CTA
#define NTHR   384
#define TSTEPS 256
#define NBLK   (TSTEPS / 2)

__device__ __forceinline__ uint32_t s2u(const void* p) {
    return (uint32_t)__cvta_generic_to_shared((void*)p);
}
__device__ __forceinline__ uint32_t mapa_u32(uint32_t a, uint32_t r) {
    uint32_t d;
    asm("mapa.shared::cluster.u32 %0, %1, %2;" : "=r"(d) : "r"(a), "r"(r));
    return d;
}
__device__ __forceinline__ void st_cluster_f32(uint32_t a, float v) {
    asm volatile("st.shared::cluster.f32 [%0], %1;" :: "r"(a), "f"(v) : "memory");
}
__device__ __forceinline__ void cl_arrive() {
    asm volatile("barrier.cluster.arrive.aligned;" ::: "memory");
}
__device__ __forceinline__ void cl_wait() {
    asm volatile("barrier.cluster.wait.aligned;" ::: "memory");
}
__device__ __forceinline__ void rgrp_bar(int id) {
    asm volatile("bar.sync %0, %1;" :: "r"(id), "r"(192) : "memory");
}

__device__ __forceinline__ float pml1(int i) {
    int d;
    if (i <= 20)           d = 20 - i;
    else if (i >= NG - 21) d = i - (NG - 21);
    else return 0.0f;
    double t = (double)d * 0.05;
    double t2 = t * t;
    return (float)(3.0 * t2 * t2);
}

__global__ void __launch_bounds__(NTHR, 1)
wave_kernel(const float* __restrict__ x, const float* __restrict__ rho,
            float* __restrict__ out)
{
    __shared__ float bufA[FROWS * P], bufB[FROWS * P], bufC[FROWS * P];
    __shared__ float halo[2][2][2][P];   // [parity][side 0=top,1=bot][idx 0=row∓1,1=row∓2][P]
    __shared__ float xs[TSTEPS];
    __shared__ float pbuf[3];

    const int tid   = threadIdx.x;
    const int col   = tid % NG;
    const int rgrp  = tid / NG;           // 0: rows 0..5 (+ext -1), 1: rows 6..11 (+ext 12)
    const int rank  = blockIdx.x % CS;
    const int batch = blockIdx.x / CS;

    for (int i = tid; i < FROWS * P; i += NTHR) { bufA[i] = 0.f; bufB[i] = 0.f; bufC[i] = 0.f; }
    for (int i = tid; i < 2*2*2*P; i += NTHR) (&halo[0][0][0][0])[i] = 0.f;
    for (int i = tid; i < TSTEPS; i += NTHR) xs[i] = x[batch * TSTEPS + i];

    // ---- coefficients for 8 stencil rows: j=0..7 <-> local row 6*rgrp + j - 1 ----
    const float HM2 = (float)(1.0 / (2.01 * 2.01));
    float Qp[8], Qm[8], Rc[8], y2[8], v[8];
#pragma unroll
    for (int j = 0; j < 8; ++j) {
        int g = rank * FROWS + rgrp * 6 + j - 1;
        int gc = min(max(g, 0), NG - 1);
        float cc = rho[gc * NG + col];
        float nn = (gc > 0)      ? rho[(gc - 1) * NG + col] : 0.f;
        float ss = (gc < NG - 1) ? rho[(gc + 1) * NG + col] : 0.f;
        float ww = (col > 0)     ? rho[gc * NG + col - 1]   : 0.f;
        float ee = (col < NG-1)  ? rho[gc * NG + col + 1]   : 0.f;
        float lpf = 0.5f * cc + 0.125f * (nn + ss + ww + ee);
        float pr  = (1.0f + tanhf(100.0f * (lpf - 0.5f))) * 0.5f;
        float c   = 1.0f - 0.1f * pr;
        float bx = pml1(gc), by = pml1(col);
        float bb = sqrtf(bx * bx + by * by);
        float A1 = 1.0f / (1.0f + 0.5f * bb);
        float Q  = A1 * (1.0f - 0.5f * bb);
        float R  = A1 * (c * c) * HM2;
        Qp[j] = 1.0f + Q - 4.0f * R;
        Qm[j] = Q;
        Rc[j] = R;
        y2[j] = 0.f; v[j] = 0.f;
    }

    const bool topR = (rgrp == 0);                 // handles CTA top halo
    const bool doUp = topR && (rank > 0);
    const bool doDn = !topR && (rank < CS - 1);
    const bool hasExt = topR ? (rank > 0) : (rank < CS - 1);

    const int side = topR ? 0 : 1;
    const float* ph1[2]; const float* ph0[2];
#pragma unroll
    for (int p = 0; p < 2; ++p) {
        ph1[p] = &halo[p][side][0][col + 2];   // y(t) row ∓1
        ph0[p] = &halo[p][side][1][col + 2];   // y(t) row ∓2
    }
    uint32_t pa1[2] = {0,0}, pa0[2] = {0,0};
    if (doUp | doDn) {
        int nr = topR ? rank - 1 : rank + 1;
        int ts = topR ? 1 : 0;
#pragma unroll
        for (int p = 0; p < 2; ++p) {
            pa1[p] = mapa_u32(s2u(&halo[p][ts][0][col + 2]), (uint32_t)nr);
            pa0[p] = mapa_u32(s2u(&halo[p][ts][1][col + 2]), (uint32_t)nr);
        }
    }

    const int ofs = rgrp * 6 * P + col + 2;   // offset of own row 0
    float* pr_ = bufA + ofs;    // y(t)
    float* pm_ = bufB + ofs;    // y(t+1)
    float* po_ = bufC + ofs;    // y(t+2)

    // Source (40,96): rank3 rgrp0 j=5. Probes (160,{48,96,144}): rank13 rgrp0 j=5.
    const bool isSrc = (rank == 3)  && topR && (col == 96);
    const bool isPrb = (rank == 13) && topR &&
                       ((col == 48) | (col == 96) | (col == 144));
    float pacc = 0.f;

    cl_arrive(); cl_wait();   // zeros + setup visible cluster-wide

    for (int b = 0; b < NBLK; ++b) {
        const int hp = b & 1, hq = hp ^ 1;
        const float xs1 = xs[2 * b];
        const float xs2 = xs[2 * b + 1];

        // ================= step 1: t -> t+1, rows j=0..7 =================
        if (topR) {
            const float* h1c = ph1[hp];
            float hc = h1c[0];                  // y(t) row -1
            float hn = ph0[hp][0];              // y(t) row -2
            float hw = h1c[-1], he = h1c[1];
            float c  = pr_[0];                  // y(t) row 0
            {   // j=0: ext row -1
                float yn = fmaf(Qp[0], hc, fmaf(-Qm[0], y2[0], Rc[0] * ((hn + c) + (hw + he))));
                if (!hasExt) yn = 0.f;
                v[0] = yn;
            }
            float n = hc;
#pragma unroll
            for (int j = 1; j < 8; ++j) {
                float s = pr_[j * P];           // rows 1..7
                float w = pr_[(j - 1) * P - 1], e = pr_[(j - 1) * P + 1];
                float yn = fmaf(Qp[j], c, fmaf(-Qm[j], y2[j], Rc[j] * ((n + s) + (w + e))));
                if (j == 5) {
                    if (isSrc) yn += xs1;
                    if (isPrb) pacc = fmaf(yn, yn, pacc);
                }
                if (j < 7) pm_[(j - 1) * P] = yn;
                v[j] = yn; y2[j] = c; n = c; c = s;
            }
        } else {
            const float* h1c = ph1[hp];
            float hc = h1c[0];                  // y(t) row 12
            float n = pr_[-2 * P];              // row 4
            float c = pr_[-P];                  // row 5
#pragma unroll
            for (int j = 0; j < 7; ++j) {
                float s = (j == 6) ? hc : pr_[j * P];   // rows 6..11, then halo
                float w = pr_[(j - 1) * P - 1], e = pr_[(j - 1) * P + 1];
                float yn = fmaf(Qp[j], c, fmaf(-Qm[j], y2[j], Rc[j] * ((n + s) + (w + e))));
                if (j >= 1) pm_[(j - 1) * P] = yn;
                v[j] = yn; y2[j] = c; n = c; c = s;
            }
            {   // j=7: ext row 12 (n = y(t) row 11 rolled, c = hc)
                float hs = ph0[hp][0];          // y(t) row 13
                float hw = h1c[-1], he = h1c[1];
                float yn = fmaf(Qp[7], c, fmaf(-Qm[7], y2[7], Rc[7] * ((n + hs) + (hw + he))));
                if (!hasExt) yn = 0.f;
                v[7] = yn;
            }
        }
        rgrp_bar(rgrp + 1);   // orders step-1 pm writes within this rgrp

        // ================= step 2: t+1 -> t+2, own rows j=1..6 ============
        auto s2 = [&](int j) -> float {
            float c = v[j];
            float w = pm_[(j - 1) * P - 1], e = pm_[(j - 1) * P + 1];
            float yn = fmaf(Qp[j], c, fmaf(-Qm[j], y2[j],
                        Rc[j] * ((v[j - 1] + v[j + 1]) + (w + e))));
            if (j == 5) {
                if (isSrc) yn += xs2;
                if (isPrb) pacc = fmaf(yn, yn, pacc);
            }
            po_[(j - 1) * P] = yn;
            y2[j] = c;
            return yn;
        };

        if (topR) {
            float a0 = s2(1), a1 = s2(2);       // rows 0, 1
            if (doUp) {
                st_cluster_f32(pa1[hq], a0);    // y(t+2) row 0  -> nbr row 12 slot
                st_cluster_f32(pa0[hq], a1);    // y(t+2) row 1  -> nbr row 13 slot
            }
        } else {
            float a0 = s2(6), a1 = s2(5);       // rows 11, 10
            if (doDn) {
                st_cluster_f32(pa1[hq], a0);    // y(t+2) row 11 -> nbr row -1 slot
                st_cluster_f32(pa0[hq], a1);    // y(t+2) row 10 -> nbr row -2 slot
            }
        }
        cl_arrive();   // release pushes; remaining rows overlap barrier

        if (topR) { s2(3); s2(4); s2(5); s2(6); }
        else      { s2(4); s2(3); s2(2); s2(1); }
        y2[0] = v[0]; y2[7] = v[7];   // advance ext-row y2 by two steps

        __syncthreads();   // po visible CTA-wide for next block's step 1
        cl_wait();         // neighbors' halo pushes visible

        float* t0 = pr_; pr_ = po_; po_ = pm_; pm_ = t0;
    }

    if (isPrb) pbuf[(col - 48) / 48] = pacc;
    __syncthreads();
    if (rank == 13 && tid == 0) {
        float a = pbuf[0], b = pbuf[1], c = pbuf[2];
        float s = a + b + c;
        out[batch * 3 + 0] = a / s;
        out[batch * 3 + 1] = b / s;
        out[batch * 3 + 2] = c / s;
    }
}

extern "C" void kernel_launch(void* const* d_in, const int* in_sizes, int n_in,
                              void* d_out, int out_size)
{
    (void)in_sizes; (void)n_in; (void)out_size;
    const float* x   = (const float*)d_in[0];   // (4,256) f32
    const float* rho = (const float*)d_in[1];   // (192,192) f32
    float* out = (float*)d_out;                 // (4,3) f32

    cudaFuncSetAttribute(wave_kernel,
                         cudaFuncAttributeNonPortableClusterSizeAllowed, 1);

    cudaLaunchConfig_t cfg = {};
    cfg.gridDim  = dim3(CS * 4, 1, 1);
    cfg.blockDim = dim3(NTHR, 1, 1);
    cfg.dynamicSmemBytes = 0;
    cudaLaunchAttribute attrs[1];
    attrs[0].id = cudaLaunchAttributeClusterDimension;
    attrs[0].val.clusterDim = {CS, 1, 1};
    cfg.attrs = attrs;
    cfg.numAttrs = 1;
    cudaLaunchKernelEx(&cfg, wave_kernel, x, rho, out);
}